// round 2
// baseline (speedup 1.0000x reference)
#include <cuda_runtime.h>
#include <math.h>

#define D_DIM 128
#define K_DIM 512
#define TM 64          // latent rows per block
#define KC 64          // emb rows per smem chunk
#define ESTRIDE 132    // padded floats per emb row in smem (conflict-free)
#define NTHREADS 256
#define SOFTMIN_BETA 10.0f

// scratch (device globals: allocation-free)
__device__ double g_sq_sum;
__device__ double g_mind_sum;
__device__ unsigned int g_counts[K_DIM];
__device__ float g_emb_sq[K_DIM];

// ---------------- init: zero accumulators, compute ||e_k||^2 ----------------
// Reference-order emulation: square rounded, then sequential scalar adds.
__global__ void vq_init_kernel(const float* __restrict__ emb) {
    int k = threadIdx.x;  // 512 threads
    if (k == 0) { g_sq_sum = 0.0; g_mind_sum = 0.0; }
    g_counts[k] = 0u;
    const float* e = emb + (size_t)k * D_DIM;
    float s = 0.f;
    for (int i = 0; i < D_DIM; ++i)
        s = __fadd_rn(s, __fmul_rn(e[i], e[i]));
    g_emb_sq[k] = s;
}

// ---------------- main kernel ----------------
// smem layout: s_lat[TM*D] | s_emb[KC*ESTRIDE] | s_dist[TM*K] | s_rowsq[TM]
__global__ void __launch_bounds__(NTHREADS) vq_main_kernel(
    const float* __restrict__ latents,
    const float* __restrict__ emb,
    float* __restrict__ out_q,
    float* __restrict__ out_ind,
    float* __restrict__ out_soft)
{
    extern __shared__ float smem[];
    float* s_lat   = smem;                        // TM*D
    float* s_emb   = s_lat + TM * D_DIM;          // KC*ESTRIDE
    float* s_dist  = s_emb + KC * ESTRIDE;        // TM*K
    float* s_rowsq = s_dist + TM * K_DIM;         // TM

    const int tid = threadIdx.x;
    const long long row0 = (long long)blockIdx.x * TM;

    // --- load latent tile (coalesced float4) ---
    {
        const float4* g = (const float4*)(latents + row0 * D_DIM);
        float4* s4 = (float4*)s_lat;
#pragma unroll
        for (int it = 0; it < (TM * D_DIM / 4) / NTHREADS; ++it)
            s4[it * NTHREADS + tid] = g[it * NTHREADS + tid];
    }
    __syncthreads();

    // --- rowsq: sequential scalar order matching reference reduce ---
    if (tid < TM) {
        const float4* lr = (const float4*)(s_lat + tid * D_DIM);
        float s = 0.f;
#pragma unroll 8
        for (int i = 0; i < D_DIM / 4; ++i) {
            float4 v = lr[i];
            s = __fadd_rn(s, __fmul_rn(v.x, v.x));
            s = __fadd_rn(s, __fmul_rn(v.y, v.y));
            s = __fadd_rn(s, __fmul_rn(v.z, v.z));
            s = __fadd_rn(s, __fmul_rn(v.w, v.w));
        }
        s_rowsq[tid] = s;
    }

    const int tx = tid & 15;   // k-group: covers k = tx + 16*j, j=0..3 (within chunk)
    const int ty = tid >> 4;   // row-group: covers r = ty + 16*i, i=0..3

    // --- dist = fl( fl(rowsq + embsq) - 2*(l.e) ), l.e = sequential-k FMA chain ---
    for (int c = 0; c < K_DIM / KC; ++c) {
        __syncthreads();
        // load emb chunk into padded smem
        {
            const float4* g = (const float4*)(emb + (size_t)c * KC * D_DIM);
#pragma unroll
            for (int it = 0; it < (KC * D_DIM / 4) / NTHREADS; ++it) {
                int idx = it * NTHREADS + tid;
                int r  = idx >> 5;       // 32 float4 per row
                int c4 = idx & 31;
                ((float4*)(s_emb + r * ESTRIDE))[c4] = g[idx];
            }
        }
        __syncthreads();

        float acc[4][4];
#pragma unroll
        for (int i = 0; i < 4; ++i)
#pragma unroll
            for (int j = 0; j < 4; ++j) acc[i][j] = 0.f;

        const float4* pa[4];
        const float4* pb[4];
#pragma unroll
        for (int i = 0; i < 4; ++i) pa[i] = (const float4*)(s_lat + (ty + 16 * i) * D_DIM);
#pragma unroll
        for (int j = 0; j < 4; ++j) pb[j] = (const float4*)(s_emb + (tx + 16 * j) * ESTRIDE);

#pragma unroll 4
        for (int d4 = 0; d4 < D_DIM / 4; ++d4) {
            float4 a[4], b[4];
#pragma unroll
            for (int i = 0; i < 4; ++i) a[i] = pa[i][d4];
#pragma unroll
            for (int j = 0; j < 4; ++j) b[j] = pb[j][d4];
#pragma unroll
            for (int i = 0; i < 4; ++i)
#pragma unroll
                for (int j = 0; j < 4; ++j) {
                    // ascending-k dependent FMA chain (exact reference order)
                    acc[i][j] = __fmaf_rn(a[i].x, b[j].x, acc[i][j]);
                    acc[i][j] = __fmaf_rn(a[i].y, b[j].y, acc[i][j]);
                    acc[i][j] = __fmaf_rn(a[i].z, b[j].z, acc[i][j]);
                    acc[i][j] = __fmaf_rn(a[i].w, b[j].w, acc[i][j]);
                }
        }

#pragma unroll
        for (int i = 0; i < 4; ++i)
#pragma unroll
            for (int j = 0; j < 4; ++j) {
                int r = ty + 16 * i;
                int kk = c * KC + tx + 16 * j;
                float t = __fadd_rn(s_rowsq[r], g_emb_sq[kk]);   // fl(A+B)
                // fl(t - 2*acc): 2*acc exact, single rounding via fmaf
                s_dist[r * K_DIM + kk] = __fmaf_rn(-2.0f, acc[i][j], t);
            }
    }
    __syncthreads();

    // --- per-row: argmin, softmax, quantize, partial reductions ---
    const int wid = tid >> 5, lane = tid & 31;
    float warp_sq = 0.f;   // sum (q-l)^2 over this warp's rows
    float warp_cm = 0.f;   // sum of dist at argmin over this warp's rows

#pragma unroll 1
    for (int i = 0; i < TM / 8; ++i) {
        int r = wid * 8 + i;
        const float* dr = s_dist + r * K_DIM;

        // local scan: 16 values per lane
        float dv[16];
        float bv = 3.4e38f; int bi = 0;
#pragma unroll
        for (int t = 0; t < 16; ++t) {
            int kidx = lane + 32 * t;
            float v = dr[kidx];
            dv[t] = v;
            if (v < bv) { bv = v; bi = kidx; }   // ascending kidx -> first-wins = lowest index
        }
        // warp argmin (lowest index on ties, matching jnp.argmin)
#pragma unroll
        for (int o = 16; o; o >>= 1) {
            float ov = __shfl_down_sync(0xffffffffu, bv, o);
            int   oi = __shfl_down_sync(0xffffffffu, bi, o);
            if (ov < bv || (ov == bv && oi < bi)) { bv = ov; bi = oi; }
        }
        bv = __shfl_sync(0xffffffffu, bv, 0);
        bi = __shfl_sync(0xffffffffu, bi, 0);

        // softmax(-beta * dist), stabilized at the min
        float ev[16];
        float sum = 0.f;
#pragma unroll
        for (int t = 0; t < 16; ++t) {
            float e = __expf(-SOFTMIN_BETA * (dv[t] - bv));
            ev[t] = e;
            sum += e;
        }
#pragma unroll
        for (int o = 16; o; o >>= 1) sum += __shfl_xor_sync(0xffffffffu, sum, o);
        float inv = 1.0f / sum;

        long long rg = row0 + r;
        float* os = out_soft + rg * K_DIM;
#pragma unroll
        for (int t = 0; t < 16; ++t) os[lane + 32 * t] = ev[t] * inv;

        // quantized = emb[argmin]; accumulate (q-l)^2
        float4 q = ((const float4*)(emb + (size_t)bi * D_DIM))[lane];
        float4 l = ((const float4*)(s_lat + r * D_DIM))[lane];
        ((float4*)(out_q + rg * D_DIM))[lane] = q;

        float dx = q.x - l.x, dy = q.y - l.y, dz = q.z - l.z, dw = q.w - l.w;
        float sq = dx * dx + dy * dy + dz * dz + dw * dw;
#pragma unroll
        for (int o = 16; o; o >>= 1)
            sq += __shfl_xor_sync(0xffffffffu, sq, o);

        if (lane == 0) {
            atomicAdd(&g_counts[bi], 1u);
            out_ind[rg] = (float)bi;
            warp_sq += sq;
            warp_cm += bv;   // dist at argmin (reference grid value)
        }
    }
    if (lane == 0) {
        atomicAdd(&g_sq_sum, (double)warp_sq);
        atomicAdd(&g_mind_sum, (double)warp_cm);
    }
}

// ---------------- finalize: scalars ----------------
__global__ void vq_fin_kernel(float* __restrict__ out_vq,
                              float* __restrict__ out_ent,
                              float* __restrict__ out_cm,
                              long long B)
{
    __shared__ float red[K_DIM];
    int k = threadIdx.x;  // 512 threads
    float p = (float)g_counts[k] / (float)B;
    red[k] = -p * logf(p + 1e-10f);
    __syncthreads();
    for (int s = K_DIM / 2; s > 0; s >>= 1) {
        if (k < s) red[k] += red[k + s];
        __syncthreads();
    }
    if (k == 0) {
        double bd = (double)B;
        // vq_loss = commitment*BETA + embedding = 1.25 * mean((q-l)^2)
        out_vq[0]  = (float)((g_sq_sum / (bd * (double)D_DIM)) * 1.25);
        out_ent[0] = red[0];
        out_cm[0]  = (float)(g_mind_sum / bd);
    }
}

extern "C" void kernel_launch(void* const* d_in, const int* in_sizes, int n_in,
                              void* d_out, int out_size)
{
    const float* latents = (const float*)d_in[0];
    const float* emb     = (const float*)d_in[1];
    long long B = (long long)in_sizes[0] / D_DIM;

    // output layout: [quantized (B*D)] [vq_loss] [entropy] [inds (B)] [soft (B*K)] [cluster_metric]
    float* out      = (float*)d_out;
    float* out_q    = out;
    float* out_vq   = out + B * D_DIM;
    float* out_ent  = out_vq + 1;
    float* out_ind  = out_ent + 1;
    float* out_soft = out_ind + B;
    float* out_cm   = out_soft + B * K_DIM;

    const size_t smem_bytes = (size_t)(TM * D_DIM + KC * ESTRIDE + TM * K_DIM + TM) * sizeof(float);
    cudaFuncSetAttribute(vq_main_kernel, cudaFuncAttributeMaxDynamicSharedMemorySize, (int)smem_bytes);

    vq_init_kernel<<<1, K_DIM>>>(emb);
    vq_main_kernel<<<(unsigned)(B / TM), NTHREADS, smem_bytes>>>(latents, emb, out_q, out_ind, out_soft);
    vq_fin_kernel<<<1, K_DIM>>>(out_vq, out_ent, out_cm, B);
}

// round 4
// speedup vs baseline: 1.2254x; 1.2254x over previous
#include <cuda_runtime.h>
#include <math.h>

#define D_DIM 128
#define K_DIM 512
#define TM 64            // latent rows per block
#define KH 256           // k per half
#define DS 32            // d per stage
#define NTHREADS 256
#define LSTRIDE 132      // s_lat row stride (floats), 16B-aligned rows
#define ESTR 258         // s_embT row stride (floats), even for 8B loads
#define SOFTMIN_BETA 10.0f

// smem float offsets
#define OFF_DIST 0
#define OFF_LAT  (TM * K_DIM)                       // 32768
#define OFF_EMBT0 (OFF_LAT + TM * LSTRIDE)          // 32768 + 8448 = 41216
#define OFF_EMBT1 (OFF_EMBT0 + DS * ESTR)           // +8256 = 49472
#define SMEM_FLOATS (OFF_EMBT1 + DS * ESTR)         // 57728 -> 230912 bytes

// scratch (device globals: allocation-free)
__device__ double g_sq_sum;
__device__ double g_mind_sum;
__device__ unsigned int g_counts[K_DIM];
__device__ float g_emb_sq[K_DIM];

__device__ __forceinline__ void fma2(unsigned long long& d, unsigned long long a,
                                     unsigned long long b, unsigned long long c) {
    asm("fma.rn.f32x2 %0, %1, %2, %3;" : "=l"(d) : "l"(a), "l"(b), "l"(c));
}
__device__ __forceinline__ unsigned long long pack2(float lo, float hi) {
    unsigned long long r;
    asm("mov.b64 %0, {%1, %2};" : "=l"(r) : "f"(lo), "f"(hi));
    return r;
}
__device__ __forceinline__ void unpack2(float& lo, float& hi, unsigned long long v) {
    asm("mov.b64 {%0, %1}, %2;" : "=f"(lo), "=f"(hi) : "l"(v));
}

// ---------------- init: zero accumulators, compute ||e_k||^2 (parallel) ----------------
// Reference-order emulation: square rounded, then sequential scalar adds.
__global__ void vq_init_kernel(const float* __restrict__ emb) {
    int k = blockIdx.x * 32 + threadIdx.x;   // grid 16 x 32
    if (k == 0) { g_sq_sum = 0.0; g_mind_sum = 0.0; }
    g_counts[k] = 0u;
    const float* e = emb + (size_t)k * D_DIM;
    float s = 0.f;
    for (int i = 0; i < D_DIM; ++i)
        s = __fadd_rn(s, __fmul_rn(e[i], e[i]));
    g_emb_sq[k] = s;
}

// ---------------- main kernel ----------------
__global__ void __launch_bounds__(NTHREADS) vq_main_kernel(
    const float* __restrict__ latents,
    const float* __restrict__ emb,
    float* __restrict__ out_q,
    float* __restrict__ out_ind,
    float* __restrict__ out_soft)
{
    extern __shared__ float smem[];
    float* s_dist = smem + OFF_DIST;          // TM x 512
    float* s_lat  = smem + OFF_LAT;           // TM x LSTRIDE (rowsq stashed at [r][128])
    float* s_embT[2] = { smem + OFF_EMBT0, smem + OFF_EMBT1 };   // DS x ESTR each

    const int tid = threadIdx.x;
    const int tx = tid & 31;   // k-lane
    const int ty = tid >> 5;   // row-group (warp id)
    const long long row0 = (long long)blockIdx.x * TM;

    // --- load latent tile (coalesced float4 -> padded smem) ---
    {
        const float4* g = (const float4*)(latents + row0 * D_DIM);
#pragma unroll
        for (int it = 0; it < (TM * D_DIM / 4) / NTHREADS; ++it) {
            int idx = it * NTHREADS + tid;
            int r = idx >> 5, c4 = idx & 31;
            *(float4*)(s_lat + r * LSTRIDE + c4 * 4) = g[idx];
        }
    }
    __syncthreads();

    // --- rowsq: sequential scalar order matching reference reduce ---
    if (tid < TM) {
        const float* lr = s_lat + tid * LSTRIDE;
        float s = 0.f;
#pragma unroll 16
        for (int i = 0; i < D_DIM; ++i)
            s = __fadd_rn(s, __fmul_rn(lr[i], lr[i]));
        s_lat[tid * LSTRIDE + D_DIM] = s;   // stash in row padding
    }

    // --- transposed emb stage fill: tile = KH k x DS d ---
    const float4* e4 = (const float4*)emb;
    auto fill = [&](int buf, int kh, int ds) {
        float* sb = s_embT[buf];
#pragma unroll
        for (int it = 0; it < (KH * DS / 4) / NTHREADS; ++it) {   // 8 iters
            int idx = it * NTHREADS + tid;
            int k = idx >> 3;           // 0..255
            int d4l = idx & 7;          // 0..7
            float4 v = e4[(size_t)(kh * KH + k) * (D_DIM / 4) + ds * (DS / 4) + d4l];
            float* c = sb + (4 * d4l) * ESTR + k;
            c[0 * ESTR] = v.x; c[1 * ESTR] = v.y; c[2 * ESTR] = v.z; c[3 * ESTR] = v.w;
        }
    };

    fill(0, 0, 0);
    __syncthreads();

    // --- GEMM: dist = fl( fl(rowsq + embsq) - 2*(l.e) ), ascending-d FMA chain per output ---
    for (int kh = 0; kh < 2; ++kh) {
        unsigned long long acc[8][4];
#pragma unroll
        for (int i = 0; i < 8; ++i)
#pragma unroll
            for (int p = 0; p < 4; ++p) acc[i][p] = 0ull;

        for (int ds = 0; ds < 4; ++ds) {
            // prefetch next stage into the other buffer
            if (ds < 3)            fill((ds + 1) & 1, kh, ds + 1);
            else if (kh == 0)      fill(0, 1, 0);

            const float* sb = s_embT[ds & 1];
#pragma unroll
            for (int j = 0; j < 8; ++j) {         // 4 depths per j
                float4 a4[8];
                const float* lp = s_lat + ty * 8 * LSTRIDE + (ds * DS + 4 * j);
#pragma unroll
                for (int i = 0; i < 8; ++i) a4[i] = *(const float4*)(lp + i * LSTRIDE);
#pragma unroll
                for (int dd = 0; dd < 4; ++dd) {
                    unsigned long long bp[4];
                    const float* bb = sb + (4 * j + dd) * ESTR + 2 * tx;
#pragma unroll
                    for (int p = 0; p < 4; ++p)
                        bp[p] = *(const unsigned long long*)(bb + 64 * p);
#pragma unroll
                    for (int i = 0; i < 8; ++i) {
                        float as = (dd == 0) ? a4[i].x : (dd == 1) ? a4[i].y
                                 : (dd == 2) ? a4[i].z : a4[i].w;
                        unsigned long long av = pack2(as, as);
#pragma unroll
                        for (int p = 0; p < 4; ++p)
                            fma2(acc[i][p], av, bp[p], acc[i][p]);
                    }
                }
            }
            __syncthreads();
        }

        // store dist for this k-half with reference rounding
#pragma unroll
        for (int i = 0; i < 8; ++i) {
            int r = ty * 8 + i;
            float rowsq = s_lat[r * LSTRIDE + D_DIM];
#pragma unroll
            for (int p = 0; p < 4; ++p) {
                int k = kh * KH + 64 * p + 2 * tx;
                float lo, hi; unpack2(lo, hi, acc[i][p]);
                float2 es = *(const float2*)(g_emb_sq + k);
                float t0 = __fadd_rn(rowsq, es.x);
                float t1 = __fadd_rn(rowsq, es.y);
                float2 dv;
                dv.x = __fmaf_rn(-2.0f, lo, t0);
                dv.y = __fmaf_rn(-2.0f, hi, t1);
                *(float2*)(s_dist + r * K_DIM + k) = dv;   // FIX: global k (incl. kh*KH)
            }
        }
    }
    __syncthreads();

    // --- per-row epilogue: argmin, softmax, quantize, partial reductions ---
    const int wid = ty, lane = tx;
    float warp_sq = 0.f;
    float warp_cm = 0.f;

#pragma unroll 1
    for (int i = 0; i < 8; ++i) {
        int r = wid * 8 + i;
        const float* dr = s_dist + r * K_DIM;

        float dv[16];
        float bv = 3.4e38f; int bi = 0;
#pragma unroll
        for (int t = 0; t < 16; ++t) {
            int kidx = lane + 32 * t;
            float v = dr[kidx];
            dv[t] = v;
            if (v < bv) { bv = v; bi = kidx; }
        }
#pragma unroll
        for (int o = 16; o; o >>= 1) {
            float ov = __shfl_down_sync(0xffffffffu, bv, o);
            int   oi = __shfl_down_sync(0xffffffffu, bi, o);
            if (ov < bv || (ov == bv && oi < bi)) { bv = ov; bi = oi; }
        }
        bv = __shfl_sync(0xffffffffu, bv, 0);
        bi = __shfl_sync(0xffffffffu, bi, 0);

        float ev[16];
        float sum = 0.f;
#pragma unroll
        for (int t = 0; t < 16; ++t) {
            float e = __expf(-SOFTMIN_BETA * (dv[t] - bv));
            ev[t] = e;
            sum += e;
        }
#pragma unroll
        for (int o = 16; o; o >>= 1) sum += __shfl_xor_sync(0xffffffffu, sum, o);
        float inv = 1.0f / sum;

        long long rg = row0 + r;
        float* os = out_soft + rg * K_DIM;
#pragma unroll
        for (int t = 0; t < 16; ++t) os[lane + 32 * t] = ev[t] * inv;

        float4 q = ((const float4*)(emb + (size_t)bi * D_DIM))[lane];
        float4 l = *(const float4*)(s_lat + r * LSTRIDE + 4 * lane);
        ((float4*)(out_q + rg * D_DIM))[lane] = q;

        float dx = q.x - l.x, dy = q.y - l.y, dz = q.z - l.z, dw = q.w - l.w;
        float sq = dx * dx + dy * dy + dz * dz + dw * dw;
#pragma unroll
        for (int o = 16; o; o >>= 1)
            sq += __shfl_xor_sync(0xffffffffu, sq, o);

        if (lane == 0) {
            atomicAdd(&g_counts[bi], 1u);
            out_ind[rg] = (float)bi;
            warp_sq += sq;
            warp_cm += bv;
        }
    }
    if (lane == 0) {
        atomicAdd(&g_sq_sum, (double)warp_sq);
        atomicAdd(&g_mind_sum, (double)warp_cm);
    }
}

// ---------------- finalize: scalars ----------------
__global__ void vq_fin_kernel(float* __restrict__ out_vq,
                              float* __restrict__ out_ent,
                              float* __restrict__ out_cm,
                              long long B)
{
    __shared__ float red[K_DIM];
    int k = threadIdx.x;
    float p = (float)g_counts[k] / (float)B;
    red[k] = -p * logf(p + 1e-10f);
    __syncthreads();
    for (int s = K_DIM / 2; s > 0; s >>= 1) {
        if (k < s) red[k] += red[k + s];
        __syncthreads();
    }
    if (k == 0) {
        double bd = (double)B;
        out_vq[0]  = (float)((g_sq_sum / (bd * (double)D_DIM)) * 1.25);
        out_ent[0] = red[0];
        out_cm[0]  = (float)(g_mind_sum / bd);
    }
}

extern "C" void kernel_launch(void* const* d_in, const int* in_sizes, int n_in,
                              void* d_out, int out_size)
{
    const float* latents = (const float*)d_in[0];
    const float* emb     = (const float*)d_in[1];
    long long B = (long long)in_sizes[0] / D_DIM;

    float* out      = (float*)d_out;
    float* out_q    = out;
    float* out_vq   = out + B * D_DIM;
    float* out_ent  = out_vq + 1;
    float* out_ind  = out_ent + 1;
    float* out_soft = out_ind + B;
    float* out_cm   = out_soft + B * K_DIM;

    const size_t smem_bytes = (size_t)SMEM_FLOATS * sizeof(float);   // 230912
    cudaFuncSetAttribute(vq_main_kernel, cudaFuncAttributeMaxDynamicSharedMemorySize, (int)smem_bytes);

    vq_init_kernel<<<16, 32>>>(emb);
    vq_main_kernel<<<(unsigned)(B / TM), NTHREADS, smem_bytes>>>(latents, emb, out_q, out_ind, out_soft);
    vq_fin_kernel<<<1, K_DIM>>>(out_vq, out_ent, out_cm, B);
}